// round 11
// baseline (speedup 1.0000x reference)
#include <cuda_runtime.h>
#include <cuda_bf16.h>
#include <math.h>
#include <stdint.h>

typedef __nv_bfloat16 bf16;

#define NN 4096
#define EE 4096
#define FF 512
#define HD 512
#define NH 8
#define NL 4
#define NC 16
#define LNEPS 1e-5f
#define CAP 128

// ---------------- scratch ----------------
__device__ float g_Y[(size_t)EE * HD];
__device__ int   g_elist[(size_t)EE * CAP];
__device__ int   g_ecnt[EE];
__device__ int   g_nlist[(size_t)NN * CAP];
__device__ int   g_ncnt[NN];
__device__ float g_Xa[NN * HD];  __device__ bf16 g_Xah[NN * HD]; __device__ bf16 g_Xal[NN * HD];
__device__ float g_Xb[NN * HD];  __device__ bf16 g_Xbh[NN * HD]; __device__ bf16 g_Xbl[NN * HD];
__device__ bf16  g_X0h[NN * FF]; __device__ bf16 g_X0l[NN * FF];
__device__ bf16  g_Qh[NN * HD];  __device__ bf16 g_Ql[NN * HD];
__device__ bf16  g_Kh[NN * HD];  __device__ bf16 g_Kl[NN * HD];
__device__ float g_Vf[NN * HD];
__device__ bf16  g_VTh[(size_t)HD * NN]; __device__ bf16 g_VTl[(size_t)HD * NN];
__device__ float g_GV[NN * HD];
__device__ bf16  g_CTXh[NN * HD]; __device__ bf16 g_CTXl[NN * HD];
__device__ float g_T[NN * HD];
__device__ float g_dv2[NN];
__device__ float g_invDE[EE];
__device__ bf16  g_WTh[17 * HD * HD]; __device__ bf16 g_WTl[17 * HD * HD];

// ---------------- helpers ----------------
__device__ __forceinline__ uint32_t smem_u32(const void* p) {
    uint32_t a;
    asm("{ .reg .u64 t; cvta.to.shared.u64 t, %1; cvt.u32.u64 %0, t; }" : "=r"(a) : "l"(p));
    return a;
}
__device__ __forceinline__ void cpa16(uint32_t dst, const void* src) {
    asm volatile("cp.async.cg.shared.global [%0], [%1], 16;\n" :: "r"(dst), "l"(src));
}
__device__ __forceinline__ void mma16816(float* c, const uint32_t* a, const uint32_t* b) {
    asm volatile(
        "mma.sync.aligned.m16n8k16.row.col.f32.bf16.bf16.f32 "
        "{%0,%1,%2,%3}, {%4,%5,%6,%7}, {%8,%9}, {%0,%1,%2,%3};\n"
        : "+f"(c[0]), "+f"(c[1]), "+f"(c[2]), "+f"(c[3])
        : "r"(a[0]), "r"(a[1]), "r"(a[2]), "r"(a[3]), "r"(b[0]), "r"(b[1]));
}
__device__ __forceinline__ uint32_t pk2(bf16 a, bf16 b) {
    union { __nv_bfloat162 v; uint32_t u; } cv;
    cv.v = __halves2bfloat162(a, b);
    return cv.u;
}
__device__ __forceinline__ bf16 tohi(float v) { return __float2bfloat16_rn(v); }
__device__ __forceinline__ bf16 tolo(float v, bf16 h) {
    return __float2bfloat16_rn(v - __bfloat162float(h));
}
__device__ __forceinline__ uint32_t mul2c(uint32_t u, __nv_bfloat162 c) {
    union { __nv_bfloat162 v; uint32_t u; } a;
    a.u = u; a.v = __hmul2(a.v, c);
    return a.u;
}

// ---------------- HMMA split GEMM, segmented outputs (512 cols/segment) ----------------
struct TG {
    const bf16 *Ah, *Al, *Bh, *Bl;
    float* C[3]; bf16* Ch[3]; bf16* Cl[3];
    const float* bias[3];
    const float* resid;       // seg 0 only
    int lda, ldb, ldr;
    float alpha, rscale;
    int K;
};

__global__ __launch_bounds__(256, 1) void hgemm_k(TG p) {
    constexpr int NT = 128;
    constexpr int NT8 = NT / 16;
    constexpr int TA = 128 * 40;
    constexpr int TB = NT * 40;
    constexpr int STG = 2 * TA + 2 * TB;
    extern __shared__ bf16 sm[];

    const int tid = threadIdx.x, lid = tid & 31, wid = tid >> 5;
    const int wm = wid & 3, wn = wid >> 2;
    const int g = lid >> 2, tg = lid & 3;
    const int m0 = blockIdx.y * 128, n0 = blockIdx.x * NT;

    float acc[2][NT8][4];
    #pragma unroll
    for (int i = 0; i < 2; i++)
        #pragma unroll
        for (int j = 0; j < NT8; j++)
            #pragma unroll
            for (int q = 0; q < 4; q++) acc[i][j][q] = 0.f;

    const int nkt = p.K >> 5;

    auto issue = [&](int kt) {
        bf16* st = sm + (kt & 1) * STG;
        uint32_t sb = smem_u32(st);
        const long long ko = (long long)kt * 32;
        for (int ch = tid; ch < 512; ch += 256) {
            int r = ch >> 2, c = ch & 3;
            uint32_t d = sb + (uint32_t)(r * 40 + c * 8) * 2;
            long long go = (long long)(m0 + r) * p.lda + ko + c * 8;
            cpa16(d, p.Ah + go);
            cpa16(d + TA * 2, p.Al + go);
        }
        for (int ch = tid; ch < NT * 4; ch += 256) {
            int r = ch >> 2, c = ch & 3;
            uint32_t d = sb + (uint32_t)(2 * TA + r * 40 + c * 8) * 2;
            long long go = (long long)(n0 + r) * p.ldb + ko + c * 8;
            cpa16(d, p.Bh + go);
            cpa16(d + TB * 2, p.Bl + go);
        }
        asm volatile("cp.async.commit_group;\n");
    };

    issue(0);
    for (int kt = 0; kt < nkt; kt++) {
        if (kt + 1 < nkt) {
            issue(kt + 1);
            asm volatile("cp.async.wait_group 1;\n");
        } else {
            asm volatile("cp.async.wait_group 0;\n");
        }
        __syncthreads();
        const bf16* st  = sm + (kt & 1) * STG;
        const bf16* sAh = st;
        const bf16* sAl = st + TA;
        const bf16* sBh = st + 2 * TA;
        const bf16* sBl = st + 2 * TA + TB;
        #pragma unroll
        for (int ks = 0; ks < 2; ks++) {
            uint32_t ah[2][4], al[2][4], bh[NT8][2], bl[NT8][2];
            #pragma unroll
            for (int mi = 0; mi < 2; mi++) {
                int r0 = (wm * 32 + mi * 16 + g) * 40 + ks * 16 + 2 * tg;
                ah[mi][0] = *(const uint32_t*)(sAh + r0);
                ah[mi][1] = *(const uint32_t*)(sAh + r0 + 320);
                ah[mi][2] = *(const uint32_t*)(sAh + r0 + 8);
                ah[mi][3] = *(const uint32_t*)(sAh + r0 + 328);
                al[mi][0] = *(const uint32_t*)(sAl + r0);
                al[mi][1] = *(const uint32_t*)(sAl + r0 + 320);
                al[mi][2] = *(const uint32_t*)(sAl + r0 + 8);
                al[mi][3] = *(const uint32_t*)(sAl + r0 + 328);
            }
            #pragma unroll
            for (int ni = 0; ni < NT8; ni++) {
                int r0 = (wn * (NT / 2) + ni * 8 + g) * 40 + ks * 16 + 2 * tg;
                bh[ni][0] = *(const uint32_t*)(sBh + r0);
                bh[ni][1] = *(const uint32_t*)(sBh + r0 + 8);
                bl[ni][0] = *(const uint32_t*)(sBl + r0);
                bl[ni][1] = *(const uint32_t*)(sBl + r0 + 8);
            }
            #pragma unroll
            for (int mi = 0; mi < 2; mi++)
                #pragma unroll
                for (int ni = 0; ni < NT8; ni++) {
                    mma16816(acc[mi][ni], ah[mi], bh[ni]);
                    mma16816(acc[mi][ni], al[mi], bh[ni]);
                    mma16816(acc[mi][ni], ah[mi], bl[ni]);
                }
        }
        __syncthreads();
    }

    #pragma unroll
    for (int mi = 0; mi < 2; mi++)
        #pragma unroll
        for (int ni = 0; ni < NT8; ni++) {
            const int n = n0 + wn * (NT / 2) + ni * 8 + 2 * tg;
            const int seg = n >> 9, nn = n & 511;
            float* Cp  = p.C[seg];
            bf16*  Chp = p.Ch[seg];
            bf16*  Clp = p.Cl[seg];
            const float* bs = p.bias[seg];
            #pragma unroll
            for (int h = 0; h < 2; h++) {
                const int m = m0 + wm * 32 + mi * 16 + g + h * 8;
                float2 v = make_float2(acc[mi][ni][h * 2 + 0] * p.alpha,
                                       acc[mi][ni][h * 2 + 1] * p.alpha);
                if (bs) {
                    float2 bb = *(const float2*)(bs + nn);
                    v.x += bb.x; v.y += bb.y;
                }
                if (p.resid && seg == 0) {
                    float2 rr = *(const float2*)(p.resid + (long long)m * p.ldr + nn);
                    v.x += p.rscale * rr.x; v.y += p.rscale * rr.y;
                }
                if (Cp) *(float2*)(Cp + (long long)m * 512 + nn) = v;
                if (Chp) {
                    bf16 h0 = tohi(v.x), h1 = tohi(v.y);
                    *(uint32_t*)(Chp + (long long)m * 512 + nn) = pk2(h0, h1);
                    *(uint32_t*)(Clp + (long long)m * 512 + nn) =
                        pk2(tolo(v.x, h0), tolo(v.y, h1));
                }
            }
        }
}

// ---------------- fused flash attention ----------------
#define FKT  9216
#define FVO  18432
#define FVS  8704
#define FSTG 35840
#define FSMEM (2 * FSTG * 2)

__global__ __launch_bounds__(256, 1) void flash_k(
    const bf16* __restrict__ Qh, const bf16* __restrict__ Ql,
    const bf16* __restrict__ Kh, const bf16* __restrict__ Kl,
    const bf16* __restrict__ VTh, const bf16* __restrict__ VTl,
    const float* __restrict__ GV,
    bf16* __restrict__ CTXh, bf16* __restrict__ CTXl) {
    extern __shared__ bf16 fsm[];
    const int tid = threadIdx.x, lid = tid & 31, wid = tid >> 5;
    const int g = lid >> 2, tg = lid & 3;
    const int h = blockIdx.y;
    const int m0 = blockIdx.x * 128;
    const int qrow = m0 + wid * 16 + g;

    uint32_t qfh[4][4], qfl[4][4];
    const __nv_bfloat162 c125 = __float2bfloat162_rn(0.125f);
    #pragma unroll
    for (int ks = 0; ks < 4; ks++) {
        int col = h * 64 + ks * 16 + 2 * tg;
        const bf16* q0 = Qh + (size_t)qrow * HD + col;
        qfh[ks][0] = mul2c(*(const uint32_t*)q0, c125);
        qfh[ks][1] = mul2c(*(const uint32_t*)(q0 + 8 * HD), c125);
        qfh[ks][2] = mul2c(*(const uint32_t*)(q0 + 8), c125);
        qfh[ks][3] = mul2c(*(const uint32_t*)(q0 + 8 * HD + 8), c125);
        const bf16* p0 = Ql + (size_t)qrow * HD + col;
        qfl[ks][0] = mul2c(*(const uint32_t*)p0, c125);
        qfl[ks][1] = mul2c(*(const uint32_t*)(p0 + 8 * HD), c125);
        qfl[ks][2] = mul2c(*(const uint32_t*)(p0 + 8), c125);
        qfl[ks][3] = mul2c(*(const uint32_t*)(p0 + 8 * HD + 8), c125);
    }

    float m0s = -1e30f, m1s = -1e30f, l0 = 0.f, l1 = 0.f;
    float cO[8][4];
    #pragma unroll
    for (int i = 0; i < 8; i++)
        #pragma unroll
        for (int q = 0; q < 4; q++) cO[i][q] = 0.f;

    auto issue = [&](int j) {
        bf16* st = fsm + (j & 1) * FSTG;
        uint32_t sb = smem_u32(st);
        const int kv0 = j * 128;
        for (int ch = tid; ch < 1024; ch += 256) {
            int r = ch >> 3, c = ch & 7;
            uint32_t d = sb + (uint32_t)(r * 72 + c * 8) * 2;
            size_t go = (size_t)(kv0 + r) * HD + h * 64 + c * 8;
            cpa16(d, Kh + go);
            cpa16(d + FKT * 2, Kl + go);
        }
        for (int ch = tid; ch < 1024; ch += 256) {
            int r = ch >> 4, c = ch & 15;
            uint32_t d = sb + (uint32_t)(FVO + r * 136 + c * 8) * 2;
            size_t go = (size_t)(h * 64 + r) * NN + kv0 + c * 8;
            cpa16(d, VTh + go);
            cpa16(d + FVS * 2, VTl + go);
        }
        asm volatile("cp.async.commit_group;\n");
    };

    issue(0);
    for (int j = 0; j < 32; j++) {
        if (j + 1 < 32) {
            issue(j + 1);
            asm volatile("cp.async.wait_group 1;\n");
        } else {
            asm volatile("cp.async.wait_group 0;\n");
        }
        __syncthreads();
        const bf16* st  = fsm + (j & 1) * FSTG;
        const bf16* sKh = st;
        const bf16* sKl = st + FKT;
        const bf16* sVh = st + FVO;
        const bf16* sVl = st + FVO + FVS;

        float cS[16][4];
        #pragma unroll
        for (int i = 0; i < 16; i++)
            #pragma unroll
            for (int q = 0; q < 4; q++) cS[i][q] = 0.f;
        #pragma unroll
        for (int ks = 0; ks < 4; ks++) {
            #pragma unroll
            for (int ni = 0; ni < 16; ni++) {
                int off = (ni * 8 + g) * 72 + ks * 16 + 2 * tg;
                uint32_t bh[2] = {*(const uint32_t*)(sKh + off),
                                  *(const uint32_t*)(sKh + off + 8)};
                uint32_t bl[2] = {*(const uint32_t*)(sKl + off),
                                  *(const uint32_t*)(sKl + off + 8)};
                mma16816(cS[ni], qfh[ks], bh);
                mma16816(cS[ni], qfl[ks], bh);
                mma16816(cS[ni], qfh[ks], bl);
            }
        }

        float mt0 = -1e30f, mt1 = -1e30f;
        #pragma unroll
        for (int ni = 0; ni < 16; ni++) {
            mt0 = fmaxf(mt0, fmaxf(cS[ni][0], cS[ni][1]));
            mt1 = fmaxf(mt1, fmaxf(cS[ni][2], cS[ni][3]));
        }
        mt0 = fmaxf(mt0, __shfl_xor_sync(0xffffffffu, mt0, 1));
        mt0 = fmaxf(mt0, __shfl_xor_sync(0xffffffffu, mt0, 2));
        mt1 = fmaxf(mt1, __shfl_xor_sync(0xffffffffu, mt1, 1));
        mt1 = fmaxf(mt1, __shfl_xor_sync(0xffffffffu, mt1, 2));
        float mn0 = fmaxf(m0s, mt0), mn1 = fmaxf(m1s, mt1);
        float sc0 = __expf(m0s - mn0), sc1 = __expf(m1s - mn1);
        l0 *= sc0; l1 *= sc1;
        #pragma unroll
        for (int nv = 0; nv < 8; nv++) {
            cO[nv][0] *= sc0; cO[nv][1] *= sc0;
            cO[nv][2] *= sc1; cO[nv][3] *= sc1;
        }
        m0s = mn0; m1s = mn1;

        #pragma unroll
        for (int ks = 0; ks < 8; ks++) {
            uint32_t pah[4], pal[4];
            #pragma unroll
            for (int half = 0; half < 2; half++) {
                int ni = 2 * ks + half;
                float p0 = __expf(cS[ni][0] - mn0);
                float p1 = __expf(cS[ni][1] - mn0);
                float p2 = __expf(cS[ni][2] - mn1);
                float p3 = __expf(cS[ni][3] - mn1);
                l0 += p0 + p1; l1 += p2 + p3;
                bf16 h0 = tohi(p0), h1 = tohi(p1), h2 = tohi(p2), h3 = tohi(p3);
                pah[2 * half + 0] = pk2(h0, h1);
                pah[2 * half + 1] = pk2(h2, h3);
                pal[2 * half + 0] = pk2(tolo(p0, h0), tolo(p1, h1));
                pal[2 * half + 1] = pk2(tolo(p2, h2), tolo(p3, h3));
            }
            #pragma unroll
            for (int nv = 0; nv < 8; nv++) {
                int off = (nv * 8 + g) * 136 + ks * 16 + 2 * tg;
                uint32_t bh[2] = {*(const uint32_t*)(sVh + off),
                                  *(const uint32_t*)(sVh + off + 8)};
                uint32_t bl[2] = {*(const uint32_t*)(sVl + off),
                                  *(const uint32_t*)(sVl + off + 8)};
                mma16816(cO[nv], pah, bh);
                mma16816(cO[nv], pal, bh);
                mma16816(cO[nv], pah, bl);
            }
        }
        __syncthreads();
    }

    l0 += __shfl_xor_sync(0xffffffffu, l0, 1);
    l0 += __shfl_xor_sync(0xffffffffu, l0, 2);
    l1 += __shfl_xor_sync(0xffffffffu, l1, 1);
    l1 += __shfl_xor_sync(0xffffffffu, l1, 2);
    float i0 = 0.5f / l0, i1 = 0.5f / l1;
    #pragma unroll
    for (int nv = 0; nv < 8; nv++) {
        int col = h * 64 + nv * 8 + 2 * tg;
        size_t o0 = (size_t)qrow * HD + col;
        size_t o1 = o0 + 8 * HD;
        float2 g0 = *(const float2*)(GV + o0);
        float2 g1 = *(const float2*)(GV + o1);
        float v0 = cO[nv][0] * i0 + g0.x, v1 = cO[nv][1] * i0 + g0.y;
        float v2 = cO[nv][2] * i1 + g1.x, v3 = cO[nv][3] * i1 + g1.y;
        bf16 h0 = tohi(v0), h1 = tohi(v1), h2 = tohi(v2), h3 = tohi(v3);
        *(uint32_t*)(CTXh + o0) = pk2(h0, h1);
        *(uint32_t*)(CTXl + o0) = pk2(tolo(v0, h0), tolo(v1, h1));
        *(uint32_t*)(CTXh + o1) = pk2(h2, h3);
        *(uint32_t*)(CTXl + o1) = pk2(tolo(v2, h2), tolo(v3, h3));
    }
}

// ---------------- adjacency build (H is binary) + degrees from counts ----------------
__global__ void zero_i_k(int* __restrict__ a, int n) {
    int i = blockIdx.x * 256 + threadIdx.x;
    if (i < n) a[i] = 0;
}
__global__ void build_k(const float* __restrict__ H,
                        int* __restrict__ elist, int* __restrict__ ecnt,
                        int* __restrict__ nlist, int* __restrict__ ncnt) {
    int i = blockIdx.x;
    int local = 0;
    for (int e4 = threadIdx.x; e4 < EE / 4; e4 += 256) {
        float4 v = *(const float4*)(H + (size_t)i * EE + 4 * e4);
        float vv[4] = {v.x, v.y, v.z, v.w};
        #pragma unroll
        for (int j = 0; j < 4; j++) {
            if (vv[j] != 0.f) {
                int e = 4 * e4 + j;
                int p = atomicAdd(&ecnt[e], 1);
                if (p < CAP) elist[(size_t)e * CAP + p] = i;
                int q = atomicAdd(&ncnt[i], 1);
                if (q < CAP) nlist[(size_t)i * CAP + q] = i == i ? e : e;
                local++;
            }
        }
    }
    (void)local;
}
__global__ void deg_k(const int* __restrict__ ecnt, const int* __restrict__ ncnt,
                      float* __restrict__ invDE, float* __restrict__ dv2) {
    int i = blockIdx.x * 256 + threadIdx.x;
    if (i < EE) invDE[i] = 1.f / (float)ecnt[i];
    if (i < NN) dv2[i] = (i == 0) ? 1.f : rsqrtf((float)ncnt[i]);
}
// Y[e,:] = invDE[e] * sum_{i in e} dv2[i] * V[i,:]
__global__ __launch_bounds__(128) void spmm_edge_k(
    const int* __restrict__ elist, const int* __restrict__ ecnt,
    const float* __restrict__ dv2, const float* __restrict__ invDE,
    const float* __restrict__ V, float* __restrict__ Y) {
    int e = blockIdx.x, t = threadIdx.x;
    int cnt = ecnt[e]; if (cnt > CAP) cnt = CAP;
    const int* lst = elist + (size_t)e * CAP;
    float4 acc = make_float4(0.f, 0.f, 0.f, 0.f);
    for (int k = 0; k < cnt; k++) {
        int i = lst[k];
        float w = dv2[i];
        float4 v = *(const float4*)(V + (size_t)i * HD + 4 * t);
        acc.x += w * v.x; acc.y += w * v.y; acc.z += w * v.z; acc.w += w * v.w;
    }
    float s = invDE[e];
    acc.x *= s; acc.y *= s; acc.z *= s; acc.w *= s;
    *(float4*)(Y + (size_t)e * HD + 4 * t) = acc;
}
// GV[i,:] = 0.5 * dv2[i] * sum_{e ni i} Y[e,:]
__global__ __launch_bounds__(128) void spmm_node_k(
    const int* __restrict__ nlist, const int* __restrict__ ncnt,
    const float* __restrict__ dv2, const float* __restrict__ Y,
    float* __restrict__ GV) {
    int i = blockIdx.x, t = threadIdx.x;
    int cnt = ncnt[i]; if (cnt > CAP) cnt = CAP;
    const int* lst = nlist + (size_t)i * CAP;
    float4 acc = make_float4(0.f, 0.f, 0.f, 0.f);
    for (int k = 0; k < cnt; k++) {
        int e = lst[k];
        float4 v = *(const float4*)(Y + (size_t)e * HD + 4 * t);
        acc.x += v.x; acc.y += v.y; acc.z += v.z; acc.w += v.w;
    }
    float s = 0.5f * dv2[i];
    acc.x *= s; acc.y *= s; acc.z *= s; acc.w *= s;
    *(float4*)(GV + (size_t)i * HD + 4 * t) = acc;
}

// ---------------- split / transpose ----------------
__global__ void split_k(const float* __restrict__ in, bf16* __restrict__ oh,
                        bf16* __restrict__ ol, long long n) {
    long long i = (long long)blockIdx.x * 256 + threadIdx.x;
    if (i >= n) return;
    float v = in[i];
    bf16 h = tohi(v);
    oh[i] = h; ol[i] = tolo(v, h);
}
__global__ void tsplit_k(const float* __restrict__ in, bf16* __restrict__ oh,
                         bf16* __restrict__ ol, int R, int C) {
    __shared__ float t[32][33];
    int c0 = blockIdx.x * 32, r0 = blockIdx.y * 32;
    int x = threadIdx.x, y = threadIdx.y;
    #pragma unroll
    for (int i = 0; i < 4; i++)
        t[y + i * 8][x] = in[(size_t)(r0 + y + i * 8) * C + c0 + x];
    __syncthreads();
    #pragma unroll
    for (int i = 0; i < 4; i++) {
        float v = t[x][y + i * 8];
        size_t o = (size_t)(c0 + y + i * 8) * R + r0 + x;
        bf16 h = tohi(v);
        oh[o] = h; ol[o] = tolo(v, h);
    }
}

// ---------------- LayerNorm + PReLU ----------------
__global__ void ln_prelu_k(const float* __restrict__ T, const float* __restrict__ g,
                           const float* __restrict__ b, const float* __restrict__ a_ptr,
                           float* __restrict__ out, bf16* __restrict__ oh,
                           bf16* __restrict__ ol) {
    int row = blockIdx.x;
    const float* t = T + (size_t)row * HD;
    __shared__ float red[128];
    int tid = threadIdx.x;
    float v[4]; float s = 0.f;
    #pragma unroll
    for (int i = 0; i < 4; i++) { v[i] = t[tid + i * 128]; s += v[i]; }
    red[tid] = s; __syncthreads();
    for (int st = 64; st > 0; st >>= 1) {
        if (tid < st) red[tid] += red[tid + st];
        __syncthreads();
    }
    float mu = red[0] / HD; __syncthreads();
    float s2 = 0.f;
    #pragma unroll
    for (int i = 0; i < 4; i++) { float d = v[i] - mu; s2 += d * d; }
    red[tid] = s2; __syncthreads();
    for (int st = 64; st > 0; st >>= 1) {
        if (tid < st) red[tid] += red[tid + st];
        __syncthreads();
    }
    float inv = rsqrtf(red[0] / HD + LNEPS);
    float a = *a_ptr;
    #pragma unroll
    for (int i = 0; i < 4; i++) {
        int c = tid + i * 128;
        float o = (v[i] - mu) * inv * g[c] + b[c];
        o = (o >= 0.f) ? o : a * o;
        size_t idx = (size_t)row * HD + c;
        out[idx] = o;
        bf16 h = tohi(o);
        oh[idx] = h; ol[idx] = tolo(o, h);
    }
}

// ---------------- classifier + log-softmax ----------------
__global__ void cls_k(const float* __restrict__ X, const float* __restrict__ W,
                      const float* __restrict__ b, float* __restrict__ out) {
    int t = threadIdx.x;
    int r = blockIdx.x * 8 + (t >> 4);
    int c = t & 15;
    const float* x = X + (size_t)r * HD;
    float acc = 0.f;
    for (int k = 0; k < HD; k++) acc += x[k] * W[k * NC + c];
    out[(size_t)r * NC + c] = acc + b[c];
}
__global__ void logsoftmax_k(const float* __restrict__ L, float* __restrict__ out) {
    int row = blockIdx.x * 256 + threadIdx.x;
    if (row >= NN) return;
    const float* l = L + (size_t)row * NC;
    float mx = -1e30f;
    #pragma unroll
    for (int i = 0; i < NC; i++) mx = fmaxf(mx, l[i]);
    float s = 0.f;
    #pragma unroll
    for (int i = 0; i < NC; i++) s += __expf(l[i] - mx);
    float lse = mx + logf(s);
    #pragma unroll
    for (int i = 0; i < NC; i++) out[(size_t)row * NC + i] = l[i] - lse;
}

// ---------------- host ----------------
static void run_hgemm(TG& p, int N) {
    dim3 grid(N / 128, NN / 128, 1);
    const int smem = 2 * (2 * 128 * 40 + 2 * 128 * 40) * 2;
    cudaFuncSetAttribute(hgemm_k, cudaFuncAttributeMaxDynamicSharedMemorySize, smem);
    hgemm_k<<<grid, 256, smem>>>(p);
}

extern "C" void kernel_launch(void* const* d_in, const int* in_sizes, int n_in,
                              void* d_out, int out_size) {
    const float* X0      = (const float*)d_in[0];
    const float* H       = (const float*)d_in[1];
    const float* w_feat  = (const float*)d_in[2];
    const float* b_feat  = (const float*)d_in[3];
    const float* Wq      = (const float*)d_in[4];
    const float* bq      = (const float*)d_in[5];
    const float* Wk      = (const float*)d_in[6];
    const float* bk      = (const float*)d_in[7];
    const float* Wv      = (const float*)d_in[8];
    const float* bv      = (const float*)d_in[9];
    const float* Wo      = (const float*)d_in[10];
    const float* bo      = (const float*)d_in[11];
    const float* ln_g    = (const float*)d_in[12];
    const float* ln_b    = (const float*)d_in[13];
    const float* prelu_a = (const float*)d_in[14];
    const float* w_cls   = (const float*)d_in[15];
    const float* b_cls   = (const float*)d_in[16];
    float* out = (float*)d_out;

    float *Y, *Xa, *Xb, *Vf, *GV, *T, *dv2, *invDE;
    int *elist, *ecnt, *nlist, *ncnt;
    bf16 *Xah, *Xal, *Xbh, *Xbl, *X0h, *X0l;
    bf16 *Qh, *Ql, *Kh, *Kl, *VTh, *VTl, *CTXh, *CTXl, *WTh, *WTl;
    cudaGetSymbolAddress((void**)&Y, g_Y);
    cudaGetSymbolAddress((void**)&elist, g_elist);
    cudaGetSymbolAddress((void**)&ecnt, g_ecnt);
    cudaGetSymbolAddress((void**)&nlist, g_nlist);
    cudaGetSymbolAddress((void**)&ncnt, g_ncnt);
    cudaGetSymbolAddress((void**)&Xa, g_Xa);
    cudaGetSymbolAddress((void**)&Xah, g_Xah);
    cudaGetSymbolAddress((void**)&Xal, g_Xal);
    cudaGetSymbolAddress((void**)&Xb, g_Xb);
    cudaGetSymbolAddress((void**)&Xbh, g_Xbh);
    cudaGetSymbolAddress((void**)&Xbl, g_Xbl);
    cudaGetSymbolAddress((void**)&X0h, g_X0h);
    cudaGetSymbolAddress((void**)&X0l, g_X0l);
    cudaGetSymbolAddress((void**)&Qh, g_Qh);
    cudaGetSymbolAddress((void**)&Ql, g_Ql);
    cudaGetSymbolAddress((void**)&Kh, g_Kh);
    cudaGetSymbolAddress((void**)&Kl, g_Kl);
    cudaGetSymbolAddress((void**)&Vf, g_Vf);
    cudaGetSymbolAddress((void**)&VTh, g_VTh);
    cudaGetSymbolAddress((void**)&VTl, g_VTl);
    cudaGetSymbolAddress((void**)&GV, g_GV);
    cudaGetSymbolAddress((void**)&CTXh, g_CTXh);
    cudaGetSymbolAddress((void**)&CTXl, g_CTXl);
    cudaGetSymbolAddress((void**)&T, g_T);
    cudaGetSymbolAddress((void**)&dv2, g_dv2);
    cudaGetSymbolAddress((void**)&invDE, g_invDE);
    cudaGetSymbolAddress((void**)&WTh, g_WTh);
    cudaGetSymbolAddress((void**)&WTl, g_WTl);

    cudaFuncSetAttribute(flash_k, cudaFuncAttributeMaxDynamicSharedMemorySize, FSMEM);

    // adjacency + degrees (single pass over H; H is binary so counts = degrees)
    zero_i_k<<<(EE + 255) / 256, 256>>>(ecnt, EE);
    zero_i_k<<<(NN + 255) / 256, 256>>>(ncnt, NN);
    build_k<<<NN, 256>>>(H, elist, ecnt, nlist, ncnt);
    deg_k<<<(NN + 255) / 256, 256>>>(ecnt, ncnt, invDE, dv2);

    // operand prep
    split_k<<<(NN * FF + 255) / 256, 256>>>(X0, X0h, X0l, (long long)NN * FF);
    dim3 tb(32, 8);
    tsplit_k<<<dim3(HD / 32, FF / 32), tb>>>(w_feat, WTh, WTl, FF, HD);
    for (int l = 0; l < NL; l++) {
        size_t w0 = (size_t)l * HD * HD;
        const float* ws[4] = {Wq + w0, Wk + w0, Wv + w0, Wo + w0};
        for (int j = 0; j < 4; j++) {
            size_t o = (1 + 4 * (size_t)l + j) * HD * HD;
            tsplit_k<<<dim3(HD / 32, HD / 32), tb>>>(ws[j], WTh + o, WTl + o, HD, HD);
        }
    }

    // input projection: Xa = X0 @ w_feat + b_feat
    {
        TG p = {};
        p.Ah = X0h; p.Al = X0l; p.Bh = WTh; p.Bl = WTl;
        p.C[0] = Xa; p.Ch[0] = Xah; p.Cl[0] = Xal;
        p.bias[0] = b_feat;
        p.lda = FF; p.ldb = FF; p.ldr = 0;
        p.alpha = 1.f; p.rscale = 0.f; p.K = FF;
        run_hgemm(p, HD);
    }

    float* xf = Xa; bf16* xh = Xah; bf16* xl = Xal;
    float* yf = Xb; bf16* yh = Xbh; bf16* yl = Xbl;
    for (int l = 0; l < NL; l++) {
        size_t wq_ = (1 + 4 * (size_t)l + 0) * HD * HD;
        size_t wo_ = (1 + 4 * (size_t)l + 3) * HD * HD;

        // fused QKV: [Q|K|V] = x @ [Wq|Wk|Wv]^T  (weight blocks contiguous in arena)
        {
            TG p = {};
            p.Ah = xh; p.Al = xl; p.Bh = WTh + wq_; p.Bl = WTl + wq_;
            p.Ch[0] = Qh; p.Cl[0] = Ql;           // seg 0 -> Q hi/lo
            p.Ch[1] = Kh; p.Cl[1] = Kl;           // seg 1 -> K hi/lo
            p.C[2] = Vf;                          // seg 2 -> V fp32
            p.bias[0] = bq + (size_t)l * HD;
            p.bias[1] = bk + (size_t)l * HD;
            p.bias[2] = bv + (size_t)l * HD;
            p.lda = HD; p.ldb = HD; p.ldr = 0;
            p.alpha = 1.f; p.rscale = 0.f; p.K = HD;
            run_hgemm(p, 3 * HD);
        }

        tsplit_k<<<dim3(HD / 32, NN / 32), tb>>>(Vf, VTh, VTl, NN, HD);

        // sparse GV
        spmm_edge_k<<<EE, 128>>>(elist, ecnt, dv2, invDE, Vf, Y);
        spmm_node_k<<<NN, 128>>>(nlist, ncnt, dv2, Y, GV);

        // fused attention: CTX = 0.5*softmax(QK^T/8)V + GV
        flash_k<<<dim3(NN / 128, NH), 256, FSMEM>>>(Qh, Ql, Kh, Kl, VTh, VTl,
                                                    GV, CTXh, CTXl);

        // T = CTX @ Wo + bo + x
        {
            TG p = {};
            p.Ah = CTXh; p.Al = CTXl; p.Bh = WTh + wo_; p.Bl = WTl + wo_;
            p.C[0] = T;
            p.bias[0] = bo + (size_t)l * HD;
            p.resid = xf;
            p.lda = HD; p.ldb = HD; p.ldr = HD;
            p.alpha = 1.f; p.rscale = 1.f; p.K = HD;
            run_hgemm(p, HD);
        }

        ln_prelu_k<<<NN, 128>>>(T, ln_g + (size_t)l * HD, ln_b + (size_t)l * HD,
                                prelu_a + l, yf, yh, yl);

        float* tf = xf; xf = yf; yf = tf;
        bf16* th = xh; xh = yh; yh = th;
        bf16* tl = xl; xl = yl; yl = tl;
    }

    cls_k<<<NN / 8, 128>>>(xf, w_cls, b_cls, T);
    logsoftmax_k<<<NN / 256, 256>>>(T, out);
}

// round 13
// speedup vs baseline: 1.5140x; 1.5140x over previous
#include <cuda_runtime.h>
#include <cuda_bf16.h>
#include <math.h>
#include <stdint.h>

typedef __nv_bfloat16 bf16;

#define NN 4096
#define EE 4096
#define FF 512
#define HD 512
#define NH 8
#define NL 4
#define NC 16
#define LNEPS 1e-5f
#define CAP 128

// ---------------- scratch ----------------
__device__ float g_Y[(size_t)EE * HD];
__device__ int   g_elist[(size_t)EE * CAP];
__device__ int   g_ecnt[EE];
__device__ int   g_nlist[(size_t)NN * CAP];
__device__ int   g_ncnt[NN];
__device__ float g_Xa[NN * HD];  __device__ bf16 g_Xah[NN * HD]; __device__ bf16 g_Xal[NN * HD];
__device__ float g_Xb[NN * HD];  __device__ bf16 g_Xbh[NN * HD]; __device__ bf16 g_Xbl[NN * HD];
__device__ bf16  g_X0h[NN * FF]; __device__ bf16 g_X0l[NN * FF];
__device__ bf16  g_Qh[NN * HD];  __device__ bf16 g_Ql[NN * HD];
__device__ bf16  g_Kh[NN * HD];  __device__ bf16 g_Kl[NN * HD];
__device__ float g_Vf[NN * HD];
__device__ bf16  g_VTh[(size_t)HD * NN]; __device__ bf16 g_VTl[(size_t)HD * NN];
__device__ float g_GV[NN * HD];
__device__ bf16  g_CTXh[NN * HD]; __device__ bf16 g_CTXl[NN * HD];
__device__ float g_T[NN * HD];
__device__ float g_dv2[NN];
__device__ float g_invDE[EE];
__device__ bf16  g_WTh[17 * HD * HD]; __device__ bf16 g_WTl[17 * HD * HD];

// ---------------- helpers ----------------
__device__ __forceinline__ uint32_t smem_u32(const void* p) {
    uint32_t a;
    asm("{ .reg .u64 t; cvta.to.shared.u64 t, %1; cvt.u32.u64 %0, t; }" : "=r"(a) : "l"(p));
    return a;
}
__device__ __forceinline__ void cpa16(uint32_t dst, const void* src) {
    asm volatile("cp.async.cg.shared.global [%0], [%1], 16;\n" :: "r"(dst), "l"(src));
}
__device__ __forceinline__ void mma16816(float* c, const uint32_t* a, const uint32_t* b) {
    asm volatile(
        "mma.sync.aligned.m16n8k16.row.col.f32.bf16.bf16.f32 "
        "{%0,%1,%2,%3}, {%4,%5,%6,%7}, {%8,%9}, {%0,%1,%2,%3};\n"
        : "+f"(c[0]), "+f"(c[1]), "+f"(c[2]), "+f"(c[3])
        : "r"(a[0]), "r"(a[1]), "r"(a[2]), "r"(a[3]), "r"(b[0]), "r"(b[1]));
}
__device__ __forceinline__ uint32_t pk2(bf16 a, bf16 b) {
    union { __nv_bfloat162 v; uint32_t u; } cv;
    cv.v = __halves2bfloat162(a, b);
    return cv.u;
}
__device__ __forceinline__ bf16 tohi(float v) { return __float2bfloat16_rn(v); }
__device__ __forceinline__ bf16 tolo(float v, bf16 h) {
    return __float2bfloat16_rn(v - __bfloat162float(h));
}
__device__ __forceinline__ uint32_t mul2c(uint32_t u, __nv_bfloat162 c) {
    union { __nv_bfloat162 v; uint32_t u; } a;
    a.u = u; a.v = __hmul2(a.v, c);
    return a.u;
}

// ---------------- HMMA split GEMM (R8 known-good version) ----------------
struct TG {
    const bf16 *Ah, *Al, *Bh, *Bl;
    float* C; bf16 *Ch; bf16 *Cl;
    const float* bias; const float* resid;
    long long sA, sB, sC, sR;
    int lda, ldb, ldc, ldr;
    float alpha, rscale;
    int K;
};

__global__ __launch_bounds__(256, 1) void hgemm_k(TG p) {
    constexpr int NT = 128;
    constexpr int NT8 = NT / 16;
    constexpr int TA = 128 * 40;
    constexpr int TB = NT * 40;
    constexpr int STG = 2 * TA + 2 * TB;
    extern __shared__ bf16 sm[];

    const int tid = threadIdx.x, lid = tid & 31, wid = tid >> 5;
    const int wm = wid & 3, wn = wid >> 2;
    const int g = lid >> 2, tg = lid & 3;
    const long long z = blockIdx.z;
    const bf16* Ah = p.Ah + z * p.sA;
    const bf16* Al = p.Al + z * p.sA;
    const bf16* Bh = p.Bh + z * p.sB;
    const bf16* Bl = p.Bl + z * p.sB;
    const int m0 = blockIdx.y * 128, n0 = blockIdx.x * NT;

    float acc[2][NT8][4];
    #pragma unroll
    for (int i = 0; i < 2; i++)
        #pragma unroll
        for (int j = 0; j < NT8; j++)
            #pragma unroll
            for (int q = 0; q < 4; q++) acc[i][j][q] = 0.f;

    const int nkt = p.K >> 5;

    auto issue = [&](int kt) {
        bf16* st = sm + (kt & 1) * STG;
        uint32_t sb = smem_u32(st);
        const long long ko = (long long)kt * 32;
        for (int ch = tid; ch < 512; ch += 256) {
            int r = ch >> 2, c = ch & 3;
            uint32_t d = sb + (uint32_t)(r * 40 + c * 8) * 2;
            long long go = (long long)(m0 + r) * p.lda + ko + c * 8;
            cpa16(d, Ah + go);
            cpa16(d + TA * 2, Al + go);
        }
        for (int ch = tid; ch < NT * 4; ch += 256) {
            int r = ch >> 2, c = ch & 3;
            uint32_t d = sb + (uint32_t)(2 * TA + r * 40 + c * 8) * 2;
            long long go = (long long)(n0 + r) * p.ldb + ko + c * 8;
            cpa16(d, Bh + go);
            cpa16(d + TB * 2, Bl + go);
        }
        asm volatile("cp.async.commit_group;\n");
    };

    issue(0);
    for (int kt = 0; kt < nkt; kt++) {
        if (kt + 1 < nkt) {
            issue(kt + 1);
            asm volatile("cp.async.wait_group 1;\n");
        } else {
            asm volatile("cp.async.wait_group 0;\n");
        }
        __syncthreads();
        const bf16* st  = sm + (kt & 1) * STG;
        const bf16* sAh = st;
        const bf16* sAl = st + TA;
        const bf16* sBh = st + 2 * TA;
        const bf16* sBl = st + 2 * TA + TB;
        #pragma unroll
        for (int ks = 0; ks < 2; ks++) {
            uint32_t ah[2][4], al[2][4], bh[NT8][2], bl[NT8][2];
            #pragma unroll
            for (int mi = 0; mi < 2; mi++) {
                int r0 = (wm * 32 + mi * 16 + g) * 40 + ks * 16 + 2 * tg;
                ah[mi][0] = *(const uint32_t*)(sAh + r0);
                ah[mi][1] = *(const uint32_t*)(sAh + r0 + 320);
                ah[mi][2] = *(const uint32_t*)(sAh + r0 + 8);
                ah[mi][3] = *(const uint32_t*)(sAh + r0 + 328);
                al[mi][0] = *(const uint32_t*)(sAl + r0);
                al[mi][1] = *(const uint32_t*)(sAl + r0 + 320);
                al[mi][2] = *(const uint32_t*)(sAl + r0 + 8);
                al[mi][3] = *(const uint32_t*)(sAl + r0 + 328);
            }
            #pragma unroll
            for (int ni = 0; ni < NT8; ni++) {
                int r0 = (wn * (NT / 2) + ni * 8 + g) * 40 + ks * 16 + 2 * tg;
                bh[ni][0] = *(const uint32_t*)(sBh + r0);
                bh[ni][1] = *(const uint32_t*)(sBh + r0 + 8);
                bl[ni][0] = *(const uint32_t*)(sBl + r0);
                bl[ni][1] = *(const uint32_t*)(sBl + r0 + 8);
            }
            #pragma unroll
            for (int mi = 0; mi < 2; mi++)
                #pragma unroll
                for (int ni = 0; ni < NT8; ni++) {
                    mma16816(acc[mi][ni], ah[mi], bh[ni]);
                    mma16816(acc[mi][ni], al[mi], bh[ni]);
                    mma16816(acc[mi][ni], ah[mi], bl[ni]);
                }
        }
        __syncthreads();
    }

    float* Cp  = p.C  ? p.C  + z * p.sC : (float*)0;
    bf16*  Chp = p.Ch ? p.Ch + z * p.sC : (bf16*)0;
    bf16*  Clp = p.Cl ? p.Cl + z * p.sC : (bf16*)0;
    const float* Rp = p.resid ? p.resid + z * p.sR : (const float*)0;

    #pragma unroll
    for (int mi = 0; mi < 2; mi++)
        #pragma unroll
        for (int ni = 0; ni < NT8; ni++) {
            const int n = n0 + wn * (NT / 2) + ni * 8 + 2 * tg;
            #pragma unroll
            for (int h = 0; h < 2; h++) {
                const int m = m0 + wm * 32 + mi * 16 + g + h * 8;
                float2 v = make_float2(acc[mi][ni][h * 2 + 0] * p.alpha,
                                       acc[mi][ni][h * 2 + 1] * p.alpha);
                if (p.bias) {
                    float2 bb = *(const float2*)(p.bias + n);
                    v.x += bb.x; v.y += bb.y;
                }
                if (Rp) {
                    float2 rr = *(const float2*)(Rp + (long long)m * p.ldr + n);
                    v.x += p.rscale * rr.x; v.y += p.rscale * rr.y;
                }
                if (Cp) *(float2*)(Cp + (long long)m * p.ldc + n) = v;
                if (Chp) {
                    bf16 h0 = tohi(v.x), h1 = tohi(v.y);
                    *(uint32_t*)(Chp + (long long)m * p.ldc + n) = pk2(h0, h1);
                    *(uint32_t*)(Clp + (long long)m * p.ldc + n) =
                        pk2(tolo(v.x, h0), tolo(v.y, h1));
                }
            }
        }
}

// ---------------- fused flash attention ----------------
#define FKT  9216
#define FVO  18432
#define FVS  8704
#define FSTG 35840
#define FSMEM (2 * FSTG * 2)

__global__ __launch_bounds__(256, 1) void flash_k(
    const bf16* __restrict__ Qh, const bf16* __restrict__ Ql,
    const bf16* __restrict__ Kh, const bf16* __restrict__ Kl,
    const bf16* __restrict__ VTh, const bf16* __restrict__ VTl,
    const float* __restrict__ GV,
    bf16* __restrict__ CTXh, bf16* __restrict__ CTXl) {
    extern __shared__ bf16 fsm[];
    const int tid = threadIdx.x, lid = tid & 31, wid = tid >> 5;
    const int g = lid >> 2, tg = lid & 3;
    const int h = blockIdx.y;
    const int m0 = blockIdx.x * 128;
    const int qrow = m0 + wid * 16 + g;

    uint32_t qfh[4][4], qfl[4][4];
    const __nv_bfloat162 c125 = __float2bfloat162_rn(0.125f);
    #pragma unroll
    for (int ks = 0; ks < 4; ks++) {
        int col = h * 64 + ks * 16 + 2 * tg;
        const bf16* q0 = Qh + (size_t)qrow * HD + col;
        qfh[ks][0] = mul2c(*(const uint32_t*)q0, c125);
        qfh[ks][1] = mul2c(*(const uint32_t*)(q0 + 8 * HD), c125);
        qfh[ks][2] = mul2c(*(const uint32_t*)(q0 + 8), c125);
        qfh[ks][3] = mul2c(*(const uint32_t*)(q0 + 8 * HD + 8), c125);
        const bf16* p0 = Ql + (size_t)qrow * HD + col;
        qfl[ks][0] = mul2c(*(const uint32_t*)p0, c125);
        qfl[ks][1] = mul2c(*(const uint32_t*)(p0 + 8 * HD), c125);
        qfl[ks][2] = mul2c(*(const uint32_t*)(p0 + 8), c125);
        qfl[ks][3] = mul2c(*(const uint32_t*)(p0 + 8 * HD + 8), c125);
    }

    float m0s = -1e30f, m1s = -1e30f, l0 = 0.f, l1 = 0.f;
    float cO[8][4];
    #pragma unroll
    for (int i = 0; i < 8; i++)
        #pragma unroll
        for (int q = 0; q < 4; q++) cO[i][q] = 0.f;

    auto issue = [&](int j) {
        bf16* st = fsm + (j & 1) * FSTG;
        uint32_t sb = smem_u32(st);
        const int kv0 = j * 128;
        for (int ch = tid; ch < 1024; ch += 256) {
            int r = ch >> 3, c = ch & 7;
            uint32_t d = sb + (uint32_t)(r * 72 + c * 8) * 2;
            size_t go = (size_t)(kv0 + r) * HD + h * 64 + c * 8;
            cpa16(d, Kh + go);
            cpa16(d + FKT * 2, Kl + go);
        }
        for (int ch = tid; ch < 1024; ch += 256) {
            int r = ch >> 4, c = ch & 15;
            uint32_t d = sb + (uint32_t)(FVO + r * 136 + c * 8) * 2;
            size_t go = (size_t)(h * 64 + r) * NN + kv0 + c * 8;
            cpa16(d, VTh + go);
            cpa16(d + FVS * 2, VTl + go);
        }
        asm volatile("cp.async.commit_group;\n");
    };

    issue(0);
    for (int j = 0; j < 32; j++) {
        if (j + 1 < 32) {
            issue(j + 1);
            asm volatile("cp.async.wait_group 1;\n");
        } else {
            asm volatile("cp.async.wait_group 0;\n");
        }
        __syncthreads();
        const bf16* st  = fsm + (j & 1) * FSTG;
        const bf16* sKh = st;
        const bf16* sKl = st + FKT;
        const bf16* sVh = st + FVO;
        const bf16* sVl = st + FVO + FVS;

        float cS[16][4];
        #pragma unroll
        for (int i = 0; i < 16; i++)
            #pragma unroll
            for (int q = 0; q < 4; q++) cS[i][q] = 0.f;
        #pragma unroll
        for (int ks = 0; ks < 4; ks++) {
            #pragma unroll
            for (int ni = 0; ni < 16; ni++) {
                int off = (ni * 8 + g) * 72 + ks * 16 + 2 * tg;
                uint32_t bh[2] = {*(const uint32_t*)(sKh + off),
                                  *(const uint32_t*)(sKh + off + 8)};
                uint32_t bl[2] = {*(const uint32_t*)(sKl + off),
                                  *(const uint32_t*)(sKl + off + 8)};
                mma16816(cS[ni], qfh[ks], bh);
                mma16816(cS[ni], qfl[ks], bh);
                mma16816(cS[ni], qfh[ks], bl);
            }
        }

        float mt0 = -1e30f, mt1 = -1e30f;
        #pragma unroll
        for (int ni = 0; ni < 16; ni++) {
            mt0 = fmaxf(mt0, fmaxf(cS[ni][0], cS[ni][1]));
            mt1 = fmaxf(mt1, fmaxf(cS[ni][2], cS[ni][3]));
        }
        mt0 = fmaxf(mt0, __shfl_xor_sync(0xffffffffu, mt0, 1));
        mt0 = fmaxf(mt0, __shfl_xor_sync(0xffffffffu, mt0, 2));
        mt1 = fmaxf(mt1, __shfl_xor_sync(0xffffffffu, mt1, 1));
        mt1 = fmaxf(mt1, __shfl_xor_sync(0xffffffffu, mt1, 2));
        float mn0 = fmaxf(m0s, mt0), mn1 = fmaxf(m1s, mt1);
        float sc0 = __expf(m0s - mn0), sc1 = __expf(m1s - mn1);
        l0 *= sc0; l1 *= sc1;
        #pragma unroll
        for (int nv = 0; nv < 8; nv++) {
            cO[nv][0] *= sc0; cO[nv][1] *= sc0;
            cO[nv][2] *= sc1; cO[nv][3] *= sc1;
        }
        m0s = mn0; m1s = mn1;

        #pragma unroll
        for (int ks = 0; ks < 8; ks++) {
            uint32_t pah[4], pal[4];
            #pragma unroll
            for (int half = 0; half < 2; half++) {
                int ni = 2 * ks + half;
                float p0 = __expf(cS[ni][0] - mn0);
                float p1 = __expf(cS[ni][1] - mn0);
                float p2 = __expf(cS[ni][2] - mn1);
                float p3 = __expf(cS[ni][3] - mn1);
                l0 += p0 + p1; l1 += p2 + p3;
                bf16 h0 = tohi(p0), h1 = tohi(p1), h2 = tohi(p2), h3 = tohi(p3);
                pah[2 * half + 0] = pk2(h0, h1);
                pah[2 * half + 1] = pk2(h2, h3);
                pal[2 * half + 0] = pk2(tolo(p0, h0), tolo(p1, h1));
                pal[2 * half + 1] = pk2(tolo(p2, h2), tolo(p3, h3));
            }
            #pragma unroll
            for (int nv = 0; nv < 8; nv++) {
                int off = (nv * 8 + g) * 136 + ks * 16 + 2 * tg;
                uint32_t bh[2] = {*(const uint32_t*)(sVh + off),
                                  *(const uint32_t*)(sVh + off + 8)};
                uint32_t bl[2] = {*(const uint32_t*)(sVl + off),
                                  *(const uint32_t*)(sVl + off + 8)};
                mma16816(cO[nv], pah, bh);
                mma16816(cO[nv], pal, bh);
                mma16816(cO[nv], pah, bl);
            }
        }
        __syncthreads();
    }

    l0 += __shfl_xor_sync(0xffffffffu, l0, 1);
    l0 += __shfl_xor_sync(0xffffffffu, l0, 2);
    l1 += __shfl_xor_sync(0xffffffffu, l1, 1);
    l1 += __shfl_xor_sync(0xffffffffu, l1, 2);
    float i0 = 0.5f / l0, i1 = 0.5f / l1;
    #pragma unroll
    for (int nv = 0; nv < 8; nv++) {
        int col = h * 64 + nv * 8 + 2 * tg;
        size_t o0 = (size_t)qrow * HD + col;
        size_t o1 = o0 + 8 * HD;
        float2 g0 = *(const float2*)(GV + o0);
        float2 g1 = *(const float2*)(GV + o1);
        float v0 = cO[nv][0] * i0 + g0.x, v1 = cO[nv][1] * i0 + g0.y;
        float v2 = cO[nv][2] * i1 + g1.x, v3 = cO[nv][3] * i1 + g1.y;
        bf16 h0 = tohi(v0), h1 = tohi(v1), h2 = tohi(v2), h3 = tohi(v3);
        *(uint32_t*)(CTXh + o0) = pk2(h0, h1);
        *(uint32_t*)(CTXl + o0) = pk2(tolo(v0, h0), tolo(v1, h1));
        *(uint32_t*)(CTXh + o1) = pk2(h2, h3);
        *(uint32_t*)(CTXl + o1) = pk2(tolo(v2, h2), tolo(v3, h3));
    }
}

// ---------------- adjacency build + degrees from counts ----------------
__global__ void zero_i_k(int* __restrict__ a, int n) {
    int i = blockIdx.x * 256 + threadIdx.x;
    if (i < n) a[i] = 0;
}
__global__ void build_k(const float* __restrict__ H,
                        int* __restrict__ elist, int* __restrict__ ecnt,
                        int* __restrict__ nlist, int* __restrict__ ncnt) {
    int i = blockIdx.x;
    for (int e4 = threadIdx.x; e4 < EE / 4; e4 += 256) {
        float4 v = *(const float4*)(H + (size_t)i * EE + 4 * e4);
        float vv[4] = {v.x, v.y, v.z, v.w};
        #pragma unroll
        for (int j = 0; j < 4; j++) {
            if (vv[j] != 0.f) {
                int e = 4 * e4 + j;
                int p = atomicAdd(&ecnt[e], 1);
                if (p < CAP) elist[(size_t)e * CAP + p] = i;
                int q = atomicAdd(&ncnt[i], 1);
                if (q < CAP) nlist[(size_t)i * CAP + q] = e;
            }
        }
    }
}
__global__ void deg_k(const int* __restrict__ ecnt, const int* __restrict__ ncnt,
                      float* __restrict__ invDE, float* __restrict__ dv2) {
    int i = blockIdx.x * 256 + threadIdx.x;
    if (i < EE) invDE[i] = 1.f / (float)ecnt[i];
    if (i < NN) dv2[i] = (i == 0) ? 1.f : rsqrtf((float)ncnt[i]);
}
// Y[e,:] = invDE[e] * sum_{i in e} dv2[i] * V[i,:]
__global__ __launch_bounds__(128) void spmm_edge_k(
    const int* __restrict__ elist, const int* __restrict__ ecnt,
    const float* __restrict__ dv2, const float* __restrict__ invDE,
    const float* __restrict__ V, float* __restrict__ Y) {
    int e = blockIdx.x, t = threadIdx.x;
    int cnt = ecnt[e]; if (cnt > CAP) cnt = CAP;
    const int* lst = elist + (size_t)e * CAP;
    float4 acc = make_float4(0.f, 0.f, 0.f, 0.f);
    for (int k = 0; k < cnt; k++) {
        int i = lst[k];
        float w = dv2[i];
        float4 v = *(const float4*)(V + (size_t)i * HD + 4 * t);
        acc.x += w * v.x; acc.y += w * v.y; acc.z += w * v.z; acc.w += w * v.w;
    }
    float s = invDE[e];
    acc.x *= s; acc.y *= s; acc.z *= s; acc.w *= s;
    *(float4*)(Y + (size_t)e * HD + 4 * t) = acc;
}
// GV[i,:] = 0.5 * dv2[i] * sum_{e ni i} Y[e,:]
__global__ __launch_bounds__(128) void spmm_node_k(
    const int* __restrict__ nlist, const int* __restrict__ ncnt,
    const float* __restrict__ dv2, const float* __restrict__ Y,
    float* __restrict__ GV) {
    int i = blockIdx.x, t = threadIdx.x;
    int cnt = ncnt[i]; if (cnt > CAP) cnt = CAP;
    const int* lst = nlist + (size_t)i * CAP;
    float4 acc = make_float4(0.f, 0.f, 0.f, 0.f);
    for (int k = 0; k < cnt; k++) {
        int e = lst[k];
        float4 v = *(const float4*)(Y + (size_t)e * HD + 4 * t);
        acc.x += v.x; acc.y += v.y; acc.z += v.z; acc.w += v.w;
    }
    float s = 0.5f * dv2[i];
    acc.x *= s; acc.y *= s; acc.z *= s; acc.w *= s;
    *(float4*)(GV + (size_t)i * HD + 4 * t) = acc;
}

// ---------------- split / transpose ----------------
__global__ void split_k(const float* __restrict__ in, bf16* __restrict__ oh,
                        bf16* __restrict__ ol, long long n) {
    long long i = (long long)blockIdx.x * 256 + threadIdx.x;
    if (i >= n) return;
    float v = in[i];
    bf16 h = tohi(v);
    oh[i] = h; ol[i] = tolo(v, h);
}
__global__ void tsplit_k(const float* __restrict__ in, bf16* __restrict__ oh,
                         bf16* __restrict__ ol, int R, int C) {
    __shared__ float t[32][33];
    int c0 = blockIdx.x * 32, r0 = blockIdx.y * 32;
    int x = threadIdx.x, y = threadIdx.y;
    #pragma unroll
    for (int i = 0; i < 4; i++)
        t[y + i * 8][x] = in[(size_t)(r0 + y + i * 8) * C + c0 + x];
    __syncthreads();
    #pragma unroll
    for (int i = 0; i < 4; i++) {
        float v = t[x][y + i * 8];
        size_t o = (size_t)(c0 + y + i * 8) * R + r0 + x;
        bf16 h = tohi(v);
        oh[o] = h; ol[o] = tolo(v, h);
    }
}

// ---------------- LayerNorm + PReLU ----------------
__global__ void ln_prelu_k(const float* __restrict__ T, const float* __restrict__ g,
                           const float* __restrict__ b, const float* __restrict__ a_ptr,
                           float* __restrict__ out, bf16* __restrict__ oh,
                           bf16* __restrict__ ol) {
    int row = blockIdx.x;
    const float* t = T + (size_t)row * HD;
    __shared__ float red[128];
    int tid = threadIdx.x;
    float v[4]; float s = 0.f;
    #pragma unroll
    for (int i = 0; i < 4; i++) { v[i] = t[tid + i * 128]; s += v[i]; }
    red[tid] = s; __syncthreads();
    for (int st = 64; st > 0; st >>= 1) {
        if (tid < st) red[tid] += red[tid + st];
        __syncthreads();
    }
    float mu = red[0] / HD; __syncthreads();
    float s2 = 0.f;
    #pragma unroll
    for (int i = 0; i < 4; i++) { float d = v[i] - mu; s2 += d * d; }
    red[tid] = s2; __syncthreads();
    for (int st = 64; st > 0; st >>= 1) {
        if (tid < st) red[tid] += red[tid + st];
        __syncthreads();
    }
    float inv = rsqrtf(red[0] / HD + LNEPS);
    float a = *a_ptr;
    #pragma unroll
    for (int i = 0; i < 4; i++) {
        int c = tid + i * 128;
        float o = (v[i] - mu) * inv * g[c] + b[c];
        o = (o >= 0.f) ? o : a * o;
        size_t idx = (size_t)row * HD + c;
        out[idx] = o;
        bf16 h = tohi(o);
        oh[idx] = h; ol[idx] = tolo(o, h);
    }
}

// ---------------- classifier + log-softmax ----------------
__global__ void cls_k(const float* __restrict__ X, const float* __restrict__ W,
                      const float* __restrict__ b, float* __restrict__ out) {
    int t = threadIdx.x;
    int r = blockIdx.x * 8 + (t >> 4);
    int c = t & 15;
    const float* x = X + (size_t)r * HD;
    float acc = 0.f;
    for (int k = 0; k < HD; k++) acc += x[k] * W[k * NC + c];
    out[(size_t)r * NC + c] = acc + b[c];
}
__global__ void logsoftmax_k(const float* __restrict__ L, float* __restrict__ out) {
    int row = blockIdx.x * 256 + threadIdx.x;
    if (row >= NN) return;
    const float* l = L + (size_t)row * NC;
    float mx = -1e30f;
    #pragma unroll
    for (int i = 0; i < NC; i++) mx = fmaxf(mx, l[i]);
    float s = 0.f;
    #pragma unroll
    for (int i = 0; i < NC; i++) s += __expf(l[i] - mx);
    float lse = mx + logf(s);
    #pragma unroll
    for (int i = 0; i < NC; i++) out[(size_t)row * NC + i] = l[i] - lse;
}

// ---------------- host ----------------
static void tg(const bf16* Ah, const bf16* Al, int lda, long long sA,
               const bf16* Bh, const bf16* Bl, int ldb, long long sB,
               float* C, bf16* Ch, bf16* Cl, int ldc, long long sC,
               const float* bias, const float* resid, int ldr, long long sR,
               float alpha, float rscale, int M, int N, int K) {
    TG p;
    p.Ah = Ah; p.Al = Al; p.Bh = Bh; p.Bl = Bl;
    p.C = C; p.Ch = Ch; p.Cl = Cl;
    p.bias = bias; p.resid = resid;
    p.sA = sA; p.sB = sB; p.sC = sC; p.sR = sR;
    p.lda = lda; p.ldb = ldb; p.ldc = ldc; p.ldr = ldr;
    p.alpha = alpha; p.rscale = rscale;
    p.K = K;
    dim3 grid(N / 128, M / 128, 1);
    const int smem = 2 * (2 * 128 * 40 + 2 * 128 * 40) * 2;
    cudaFuncSetAttribute(hgemm_k, cudaFuncAttributeMaxDynamicSharedMemorySize, smem);
    hgemm_k<<<grid, 256, smem>>>(p);
}

extern "C" void kernel_launch(void* const* d_in, const int* in_sizes, int n_in,
                              void* d_out, int out_size) {
    const float* X0      = (const float*)d_in[0];
    const float* H       = (const float*)d_in[1];
    const float* w_feat  = (const float*)d_in[2];
    const float* b_feat  = (const float*)d_in[3];
    const float* Wq      = (const float*)d_in[4];
    const float* bq      = (const float*)d_in[5];
    const float* Wk      = (const float*)d_in[6];
    const float* bk      = (const float*)d_in[7];
    const float* Wv      = (const float*)d_in[8];
    const float* bv      = (const float*)d_in[9];
    const float* Wo      = (const float*)d_in[10];
    const float* bo      = (const float*)d_in[11];
    const float* ln_g    = (const float*)d_in[12];
    const float* ln_b    = (const float*)d_in[13];
    const float* prelu_a = (const float*)d_in[14];
    const float* w_cls   = (const float*)d_in[15];
    const float* b_cls   = (const float*)d_in[16];
    float* out = (float*)d_out;

    float *Y, *Xa, *Xb, *Vf, *GV, *T, *dv2, *invDE;
    int *elist, *ecnt, *nlist, *ncnt;
    bf16 *Xah, *Xal, *Xbh, *Xbl, *X0h, *X0l;
    bf16 *Qh, *Ql, *Kh, *Kl, *VTh, *VTl, *CTXh, *CTXl, *WTh, *WTl;
    cudaGetSymbolAddress((void**)&Y, g_Y);
    cudaGetSymbolAddress((void**)&elist, g_elist);
    cudaGetSymbolAddress((void**)&ecnt, g_ecnt);
    cudaGetSymbolAddress((void**)&nlist, g_nlist);
    cudaGetSymbolAddress((void**)&ncnt, g_ncnt);
    cudaGetSymbolAddress((void**)&Xa, g_Xa);
    cudaGetSymbolAddress((void**)&Xah, g_Xah);
    cudaGetSymbolAddress((void**)&Xal, g_Xal);
    cudaGetSymbolAddress((void**)&Xb, g_Xb);
    cudaGetSymbolAddress((void**)&Xbh, g_Xbh);
    cudaGetSymbolAddress((void**)&Xbl, g_Xbl);
    cudaGetSymbolAddress((void**)&X0h, g_X0h);
    cudaGetSymbolAddress((void**)&X0l, g_X0l);
    cudaGetSymbolAddress((void**)&Qh, g_Qh);
    cudaGetSymbolAddress((void**)&Ql, g_Ql);
    cudaGetSymbolAddress((void**)&Kh, g_Kh);
    cudaGetSymbolAddress((void**)&Kl, g_Kl);
    cudaGetSymbolAddress((void**)&Vf, g_Vf);
    cudaGetSymbolAddress((void**)&VTh, g_VTh);
    cudaGetSymbolAddress((void**)&VTl, g_VTl);
    cudaGetSymbolAddress((void**)&GV, g_GV);
    cudaGetSymbolAddress((void**)&CTXh, g_CTXh);
    cudaGetSymbolAddress((void**)&CTXl, g_CTXl);
    cudaGetSymbolAddress((void**)&T, g_T);
    cudaGetSymbolAddress((void**)&dv2, g_dv2);
    cudaGetSymbolAddress((void**)&invDE, g_invDE);
    cudaGetSymbolAddress((void**)&WTh, g_WTh);
    cudaGetSymbolAddress((void**)&WTl, g_WTl);

    cudaFuncSetAttribute(flash_k, cudaFuncAttributeMaxDynamicSharedMemorySize, FSMEM);

    // adjacency + degrees (H binary: counts ARE degrees; no dense column/row sums)
    zero_i_k<<<(EE + 255) / 256, 256>>>(ecnt, EE);
    zero_i_k<<<(NN + 255) / 256, 256>>>(ncnt, NN);
    build_k<<<NN, 256>>>(H, elist, ecnt, nlist, ncnt);
    deg_k<<<(NN + 255) / 256, 256>>>(ecnt, ncnt, invDE, dv2);

    // operand prep
    split_k<<<(NN * FF + 255) / 256, 256>>>(X0, X0h, X0l, (long long)NN * FF);
    dim3 tb(32, 8);
    tsplit_k<<<dim3(HD / 32, FF / 32), tb>>>(w_feat, WTh, WTl, FF, HD);
    for (int l = 0; l < NL; l++) {
        size_t w0 = (size_t)l * HD * HD;
        const float* ws[4] = {Wq + w0, Wk + w0, Wv + w0, Wo + w0};
        for (int j = 0; j < 4; j++) {
            size_t o = (1 + 4 * (size_t)l + j) * HD * HD;
            tsplit_k<<<dim3(HD / 32, HD / 32), tb>>>(ws[j], WTh + o, WTl + o, HD, HD);
        }
    }

    // input projection
    tg(X0h, X0l, FF, 0, WTh, WTl, FF, 0,
       Xa, Xah, Xal, HD, 0, b_feat, 0, 0, 0, 1.f, 0.f, NN, HD, FF);

    float* xf = Xa; bf16* xh = Xah; bf16* xl = Xal;
    float* yf = Xb; bf16* yh = Xbh; bf16* yl = Xbl;
    for (int l = 0; l < NL; l++) {
        size_t wq_ = (1 + 4 * (size_t)l + 0) * HD * HD;
        size_t wk_ = (1 + 4 * (size_t)l + 1) * HD * HD;
        size_t wv_ = (1 + 4 * (size_t)l + 2) * HD * HD;
        size_t wo_ = (1 + 4 * (size_t)l + 3) * HD * HD;

        tg(xh, xl, HD, 0, WTh + wq_, WTl + wq_, HD, 0,
           0, Qh, Ql, HD, 0, bq + (size_t)l * HD, 0, 0, 0, 1.f, 0.f, NN, HD, HD);
        tg(xh, xl, HD, 0, WTh + wk_, WTl + wk_, HD, 0,
           0, Kh, Kl, HD, 0, bk + (size_t)l * HD, 0, 0, 0, 1.f, 0.f, NN, HD, HD);
        tg(xh, xl, HD, 0, WTh + wv_, WTl + wv_, HD, 0,
           Vf, 0, 0, HD, 0, bv + (size_t)l * HD, 0, 0, 0, 1.f, 0.f, NN, HD, HD);

        tsplit_k<<<dim3(HD / 32, NN / 32), tb>>>(Vf, VTh, VTl, NN, HD);

        // sparse GV
        spmm_edge_k<<<EE, 128>>>(elist, ecnt, dv2, invDE, Vf, Y);
        spmm_node_k<<<NN, 128>>>(nlist, ncnt, dv2, Y, GV);

        // fused attention: CTX = 0.5*softmax(QK^T/8)V + GV
        flash_k<<<dim3(NN / 128, NH), 256, FSMEM>>>(Qh, Ql, Kh, Kl, VTh, VTl,
                                                    GV, CTXh, CTXl);

        // T = CTX @ Wo + bo + x
        tg(CTXh, CTXl, HD, 0, WTh + wo_, WTl + wo_, HD, 0,
           T, 0, 0, HD, 0, bo + (size_t)l * HD, xf, HD, 0, 1.f, 1.f, NN, HD, HD);

        ln_prelu_k<<<NN, 128>>>(T, ln_g + (size_t)l * HD, ln_b + (size_t)l * HD,
                                prelu_a + l, yf, yh, yl);

        float* tf = xf; xf = yf; yf = tf;
        bf16* th = xh; xh = yh; yh = th;
        bf16* tl = xl; xl = yl; yl = tl;
    }

    cls_k<<<NN / 8, 128>>>(xf, w_cls, b_cls, T);
    logsoftmax_k<<<NN / 256, 256>>>(T, out);
}

// round 14
// speedup vs baseline: 2.8351x; 1.8726x over previous
#include <cuda_runtime.h>
#include <cuda_fp16.h>
#include <math.h>
#include <stdint.h>

typedef __half h16;

#define NN 4096
#define EE 4096
#define FF 512
#define HD 512
#define NH 8
#define NL 4
#define NC 16
#define LNEPS 1e-5f
#define CAP 128

// ---------------- scratch ----------------
__device__ float g_Y[(size_t)EE * HD];
__device__ int   g_elist[(size_t)EE * CAP];
__device__ int   g_ecnt[EE];
__device__ int   g_nlist[(size_t)NN * CAP];
__device__ int   g_ncnt[NN];
__device__ float g_Xa[NN * HD];  __device__ h16 g_Xah[NN * HD];
__device__ float g_Xb[NN * HD];  __device__ h16 g_Xbh[NN * HD];
__device__ h16   g_X0h[NN * FF];
__device__ h16   g_Qh[NN * HD];
__device__ h16   g_Kh[NN * HD];
__device__ float g_Vf[NN * HD];
__device__ h16   g_VTh[(size_t)HD * NN];
__device__ float g_GV[NN * HD];
__device__ h16   g_CTXh[NN * HD];
__device__ float g_T[NN * HD];
__device__ float g_dv2[NN];
__device__ float g_invDE[EE];
__device__ h16   g_WTh[17 * HD * HD];

// ---------------- helpers ----------------
__device__ __forceinline__ uint32_t smem_u32(const void* p) {
    uint32_t a;
    asm("{ .reg .u64 t; cvta.to.shared.u64 t, %1; cvt.u32.u64 %0, t; }" : "=r"(a) : "l"(p));
    return a;
}
__device__ __forceinline__ void cpa16(uint32_t dst, const void* src) {
    asm volatile("cp.async.cg.shared.global [%0], [%1], 16;\n" :: "r"(dst), "l"(src));
}
__device__ __forceinline__ void mma16816(float* c, const uint32_t* a, const uint32_t* b) {
    asm volatile(
        "mma.sync.aligned.m16n8k16.row.col.f32.f16.f16.f32 "
        "{%0,%1,%2,%3}, {%4,%5,%6,%7}, {%8,%9}, {%0,%1,%2,%3};\n"
        : "+f"(c[0]), "+f"(c[1]), "+f"(c[2]), "+f"(c[3])
        : "r"(a[0]), "r"(a[1]), "r"(a[2]), "r"(a[3]), "r"(b[0]), "r"(b[1]));
}
__device__ __forceinline__ uint32_t pk2(h16 a, h16 b) {
    union { __half2 v; uint32_t u; } cv;
    cv.v = __halves2half2(a, b);
    return cv.u;
}
__device__ __forceinline__ h16 toh(float v) { return __float2half_rn(v); }
__device__ __forceinline__ uint32_t mul2c(uint32_t u, __half2 c) {
    union { __half2 v; uint32_t u; } a;
    a.u = u; a.v = __hmul2(a.v, c);
    return a.u;
}

// ---------------- fp16 HMMA GEMM ----------------
// C = alpha * A @ B^T (+bias) (+rscale*R); A [M,K] fp16, B [N,K] fp16 K-major
struct TG {
    const h16 *Ah, *Bh;
    float* C; h16* Ch;
    const float* bias; const float* resid;
    long long sA, sB, sC, sR;
    int lda, ldb, ldc, ldr;
    float alpha, rscale;
    int K;
};

__global__ __launch_bounds__(256, 1) void hgemm_k(TG p) {
    constexpr int NT = 128;
    constexpr int NT8 = NT / 16;
    constexpr int TA = 128 * 40;
    constexpr int TB = NT * 40;
    constexpr int STG = TA + TB;
    extern __shared__ h16 sm[];

    const int tid = threadIdx.x, lid = tid & 31, wid = tid >> 5;
    const int wm = wid & 3, wn = wid >> 2;
    const int g = lid >> 2, tg = lid & 3;
    const long long z = blockIdx.z;
    const h16* Ah = p.Ah + z * p.sA;
    const h16* Bh = p.Bh + z * p.sB;
    const int m0 = blockIdx.y * 128, n0 = blockIdx.x * NT;

    float acc[2][NT8][4];
    #pragma unroll
    for (int i = 0; i < 2; i++)
        #pragma unroll
        for (int j = 0; j < NT8; j++)
            #pragma unroll
            for (int q = 0; q < 4; q++) acc[i][j][q] = 0.f;

    const int nkt = p.K >> 5;

    auto issue = [&](int kt) {
        h16* st = sm + (kt & 1) * STG;
        uint32_t sb = smem_u32(st);
        const long long ko = (long long)kt * 32;
        for (int ch = tid; ch < 512; ch += 256) {
            int r = ch >> 2, c = ch & 3;
            cpa16(sb + (uint32_t)(r * 40 + c * 8) * 2,
                  Ah + (long long)(m0 + r) * p.lda + ko + c * 8);
        }
        for (int ch = tid; ch < NT * 4; ch += 256) {
            int r = ch >> 2, c = ch & 3;
            cpa16(sb + (uint32_t)(TA + r * 40 + c * 8) * 2,
                  Bh + (long long)(n0 + r) * p.ldb + ko + c * 8);
        }
        asm volatile("cp.async.commit_group;\n");
    };

    issue(0);
    for (int kt = 0; kt < nkt; kt++) {
        if (kt + 1 < nkt) {
            issue(kt + 1);
            asm volatile("cp.async.wait_group 1;\n");
        } else {
            asm volatile("cp.async.wait_group 0;\n");
        }
        __syncthreads();
        const h16* st  = sm + (kt & 1) * STG;
        const h16* sAh = st;
        const h16* sBh = st + TA;
        #pragma unroll
        for (int ks = 0; ks < 2; ks++) {
            uint32_t ah[2][4], bh[NT8][2];
            #pragma unroll
            for (int mi = 0; mi < 2; mi++) {
                int r0 = (wm * 32 + mi * 16 + g) * 40 + ks * 16 + 2 * tg;
                ah[mi][0] = *(const uint32_t*)(sAh + r0);
                ah[mi][1] = *(const uint32_t*)(sAh + r0 + 320);
                ah[mi][2] = *(const uint32_t*)(sAh + r0 + 8);
                ah[mi][3] = *(const uint32_t*)(sAh + r0 + 328);
            }
            #pragma unroll
            for (int ni = 0; ni < NT8; ni++) {
                int r0 = (wn * (NT / 2) + ni * 8 + g) * 40 + ks * 16 + 2 * tg;
                bh[ni][0] = *(const uint32_t*)(sBh + r0);
                bh[ni][1] = *(const uint32_t*)(sBh + r0 + 8);
            }
            #pragma unroll
            for (int mi = 0; mi < 2; mi++)
                #pragma unroll
                for (int ni = 0; ni < NT8; ni++)
                    mma16816(acc[mi][ni], ah[mi], bh[ni]);
        }
        __syncthreads();
    }

    float* Cp  = p.C  ? p.C  + z * p.sC : (float*)0;
    h16*   Chp = p.Ch ? p.Ch + z * p.sC : (h16*)0;
    const float* Rp = p.resid ? p.resid + z * p.sR : (const float*)0;

    #pragma unroll
    for (int mi = 0; mi < 2; mi++)
        #pragma unroll
        for (int ni = 0; ni < NT8; ni++) {
            const int n = n0 + wn * (NT / 2) + ni * 8 + 2 * tg;
            #pragma unroll
            for (int h = 0; h < 2; h++) {
                const int m = m0 + wm * 32 + mi * 16 + g + h * 8;
                float2 v = make_float2(acc[mi][ni][h * 2 + 0] * p.alpha,
                                       acc[mi][ni][h * 2 + 1] * p.alpha);
                if (p.bias) {
                    float2 bb = *(const float2*)(p.bias + n);
                    v.x += bb.x; v.y += bb.y;
                }
                if (Rp) {
                    float2 rr = *(const float2*)(Rp + (long long)m * p.ldr + n);
                    v.x += p.rscale * rr.x; v.y += p.rscale * rr.y;
                }
                if (Cp) *(float2*)(Cp + (long long)m * p.ldc + n) = v;
                if (Chp)
                    *(uint32_t*)(Chp + (long long)m * p.ldc + n) =
                        pk2(toh(v.x), toh(v.y));
            }
        }
}

// ---------------- fused flash attention (fp16) ----------------
#define FVO  9216             // V tile offset (elems): K tile 128*72
#define FSTG 17920            // stage elems: 9216 + 64*136
#define FSMEM (2 * FSTG * 2)

__global__ __launch_bounds__(256) void flash_k(
    const h16* __restrict__ Qh, const h16* __restrict__ Kh,
    const h16* __restrict__ VTh, const float* __restrict__ GV,
    h16* __restrict__ CTXh) {
    extern __shared__ h16 fsm[];
    const int tid = threadIdx.x, lid = tid & 31, wid = tid >> 5;
    const int g = lid >> 2, tg = lid & 3;
    const int h = blockIdx.y;
    const int m0 = blockIdx.x * 128;
    const int qrow = m0 + wid * 16 + g;

    uint32_t qf[4][4];
    const __half2 c125 = __float2half2_rn(0.125f);
    #pragma unroll
    for (int ks = 0; ks < 4; ks++) {
        int col = h * 64 + ks * 16 + 2 * tg;
        const h16* q0 = Qh + (size_t)qrow * HD + col;
        qf[ks][0] = mul2c(*(const uint32_t*)q0, c125);
        qf[ks][1] = mul2c(*(const uint32_t*)(q0 + 8 * HD), c125);
        qf[ks][2] = mul2c(*(const uint32_t*)(q0 + 8), c125);
        qf[ks][3] = mul2c(*(const uint32_t*)(q0 + 8 * HD + 8), c125);
    }

    float m0s = -1e30f, m1s = -1e30f, l0 = 0.f, l1 = 0.f;
    float cO[8][4];
    #pragma unroll
    for (int i = 0; i < 8; i++)
        #pragma unroll
        for (int q = 0; q < 4; q++) cO[i][q] = 0.f;

    auto issue = [&](int j) {
        h16* st = fsm + (j & 1) * FSTG;
        uint32_t sb = smem_u32(st);
        const int kv0 = j * 128;
        for (int ch = tid; ch < 1024; ch += 256) {
            int r = ch >> 3, c = ch & 7;
            cpa16(sb + (uint32_t)(r * 72 + c * 8) * 2,
                  Kh + (size_t)(kv0 + r) * HD + h * 64 + c * 8);
        }
        for (int ch = tid; ch < 1024; ch += 256) {
            int r = ch >> 4, c = ch & 15;
            cpa16(sb + (uint32_t)(FVO + r * 136 + c * 8) * 2,
                  VTh + (size_t)(h * 64 + r) * NN + kv0 + c * 8);
        }
        asm volatile("cp.async.commit_group;\n");
    };

    issue(0);
    for (int j = 0; j < 32; j++) {
        if (j + 1 < 32) {
            issue(j + 1);
            asm volatile("cp.async.wait_group 1;\n");
        } else {
            asm volatile("cp.async.wait_group 0;\n");
        }
        __syncthreads();
        const h16* st = fsm + (j & 1) * FSTG;
        const h16* sK = st;
        const h16* sV = st + FVO;

        float cS[16][4];
        #pragma unroll
        for (int i = 0; i < 16; i++)
            #pragma unroll
            for (int q = 0; q < 4; q++) cS[i][q] = 0.f;
        #pragma unroll
        for (int ks = 0; ks < 4; ks++) {
            #pragma unroll
            for (int ni = 0; ni < 16; ni++) {
                int off = (ni * 8 + g) * 72 + ks * 16 + 2 * tg;
                uint32_t bh[2] = {*(const uint32_t*)(sK + off),
                                  *(const uint32_t*)(sK + off + 8)};
                mma16816(cS[ni], qf[ks], bh);
            }
        }

        float mt0 = -1e30f, mt1 = -1e30f;
        #pragma unroll
        for (int ni = 0; ni < 16; ni++) {
            mt0 = fmaxf(mt0, fmaxf(cS[ni][0], cS[ni][1]));
            mt1 = fmaxf(mt1, fmaxf(cS[ni][2], cS[ni][3]));
        }
        mt0 = fmaxf(mt0, __shfl_xor_sync(0xffffffffu, mt0, 1));
        mt0 = fmaxf(mt0, __shfl_xor_sync(0xffffffffu, mt0, 2));
        mt1 = fmaxf(mt1, __shfl_xor_sync(0xffffffffu, mt1, 1));
        mt1 = fmaxf(mt1, __shfl_xor_sync(0xffffffffu, mt1, 2));
        float mn0 = fmaxf(m0s, mt0), mn1 = fmaxf(m1s, mt1);
        float sc0 = __expf(m0s - mn0), sc1 = __expf(m1s - mn1);
        l0 *= sc0; l1 *= sc1;
        #pragma unroll
        for (int nv = 0; nv < 8; nv++) {
            cO[nv][0] *= sc0; cO[nv][1] *= sc0;
            cO[nv][2] *= sc1; cO[nv][3] *= sc1;
        }
        m0s = mn0; m1s = mn1;

        #pragma unroll
        for (int ks = 0; ks < 8; ks++) {
            uint32_t pa[4];
            #pragma unroll
            for (int half = 0; half < 2; half++) {
                int ni = 2 * ks + half;
                float p0 = __expf(cS[ni][0] - mn0);
                float p1 = __expf(cS[ni][1] - mn0);
                float p2 = __expf(cS[ni][2] - mn1);
                float p3 = __expf(cS[ni][3] - mn1);
                l0 += p0 + p1; l1 += p2 + p3;
                pa[2 * half + 0] = pk2(toh(p0), toh(p1));
                pa[2 * half + 1] = pk2(toh(p2), toh(p3));
            }
            #pragma unroll
            for (int nv = 0; nv < 8; nv++) {
                int off = (nv * 8 + g) * 136 + ks * 16 + 2 * tg;
                uint32_t bh[2] = {*(const uint32_t*)(sV + off),
                                  *(const uint32_t*)(sV + off + 8)};
                mma16816(cO[nv], pa, bh);
            }
        }
        __syncthreads();
    }

    l0 += __shfl_xor_sync(0xffffffffu, l0, 1);
    l0 += __shfl_xor_sync(0xffffffffu, l0, 2);
    l1 += __shfl_xor_sync(0xffffffffu, l1, 1);
    l1 += __shfl_xor_sync(0xffffffffu, l1, 2);
    float i0 = 0.5f / l0, i1 = 0.5f / l1;
    #pragma unroll
    for (int nv = 0; nv < 8; nv++) {
        int col = h * 64 + nv * 8 + 2 * tg;
        size_t o0 = (size_t)qrow * HD + col;
        size_t o1 = o0 + 8 * HD;
        float2 g0 = *(const float2*)(GV + o0);
        float2 g1 = *(const float2*)(GV + o1);
        *(uint32_t*)(CTXh + o0) = pk2(toh(cO[nv][0] * i0 + g0.x),
                                      toh(cO[nv][1] * i0 + g0.y));
        *(uint32_t*)(CTXh + o1) = pk2(toh(cO[nv][2] * i1 + g1.x),
                                      toh(cO[nv][3] * i1 + g1.y));
    }
}

// ---------------- adjacency build + degrees from counts ----------------
__global__ void zero_i_k(int* __restrict__ a, int n) {
    int i = blockIdx.x * 256 + threadIdx.x;
    if (i < n) a[i] = 0;
}
__global__ void build_k(const float* __restrict__ H,
                        int* __restrict__ elist, int* __restrict__ ecnt,
                        int* __restrict__ nlist, int* __restrict__ ncnt) {
    int i = blockIdx.x;
    for (int e4 = threadIdx.x; e4 < EE / 4; e4 += 256) {
        float4 v = *(const float4*)(H + (size_t)i * EE + 4 * e4);
        float vv[4] = {v.x, v.y, v.z, v.w};
        #pragma unroll
        for (int j = 0; j < 4; j++) {
            if (vv[j] != 0.f) {
                int e = 4 * e4 + j;
                int p = atomicAdd(&ecnt[e], 1);
                if (p < CAP) elist[(size_t)e * CAP + p] = i;
                int q = atomicAdd(&ncnt[i], 1);
                if (q < CAP) nlist[(size_t)i * CAP + q] = e;
            }
        }
    }
}
__global__ void deg_k(const int* __restrict__ ecnt, const int* __restrict__ ncnt,
                      float* __restrict__ invDE, float* __restrict__ dv2) {
    int i = blockIdx.x * 256 + threadIdx.x;
    if (i < EE) invDE[i] = 1.f / (float)ecnt[i];
    if (i < NN) dv2[i] = (i == 0) ? 1.f : rsqrtf((float)ncnt[i]);
}
__global__ __launch_bounds__(128) void spmm_edge_k(
    const int* __restrict__ elist, const int* __restrict__ ecnt,
    const float* __restrict__ dv2, const float* __restrict__ invDE,
    const float* __restrict__ V, float* __restrict__ Y) {
    int e = blockIdx.x, t = threadIdx.x;
    int cnt = ecnt[e]; if (cnt > CAP) cnt = CAP;
    const int* lst = elist + (size_t)e * CAP;
    float4 acc = make_float4(0.f, 0.f, 0.f, 0.f);
    for (int k = 0; k < cnt; k++) {
        int i = lst[k];
        float w = dv2[i];
        float4 v = *(const float4*)(V + (size_t)i * HD + 4 * t);
        acc.x += w * v.x; acc.y += w * v.y; acc.z += w * v.z; acc.w += w * v.w;
    }
    float s = invDE[e];
    acc.x *= s; acc.y *= s; acc.z *= s; acc.w *= s;
    *(float4*)(Y + (size_t)e * HD + 4 * t) = acc;
}
__global__ __launch_bounds__(128) void spmm_node_k(
    const int* __restrict__ nlist, const int* __restrict__ ncnt,
    const float* __restrict__ dv2, const float* __restrict__ Y,
    float* __restrict__ GV) {
    int i = blockIdx.x, t = threadIdx.x;
    int cnt = ncnt[i]; if (cnt > CAP) cnt = CAP;
    const int* lst = nlist + (size_t)i * CAP;
    float4 acc = make_float4(0.f, 0.f, 0.f, 0.f);
    for (int k = 0; k < cnt; k++) {
        int e = lst[k];
        float4 v = *(const float4*)(Y + (size_t)e * HD + 4 * t);
        acc.x += v.x; acc.y += v.y; acc.z += v.z; acc.w += v.w;
    }
    float s = 0.5f * dv2[i];
    acc.x *= s; acc.y *= s; acc.z *= s; acc.w *= s;
    *(float4*)(GV + (size_t)i * HD + 4 * t) = acc;
}

// ---------------- convert / transpose ----------------
__global__ void split_k(const float* __restrict__ in, h16* __restrict__ oh,
                        long long n) {
    long long i = (long long)blockIdx.x * 256 + threadIdx.x;
    if (i >= n) return;
    oh[i] = toh(in[i]);
}
__global__ void tsplit_k(const float* __restrict__ in, h16* __restrict__ oh,
                         int R, int C) {
    __shared__ float t[32][33];
    int c0 = blockIdx.x * 32, r0 = blockIdx.y * 32;
    int x = threadIdx.x, y = threadIdx.y;
    #pragma unroll
    for (int i = 0; i < 4; i++)
        t[y + i * 8][x] = in[(size_t)(r0 + y + i * 8) * C + c0 + x];
    __syncthreads();
    #pragma unroll
    for (int i = 0; i < 4; i++)
        oh[(size_t)(c0 + y + i * 8) * R + r0 + x] = toh(t[x][y + i * 8]);
}

// ---------------- LayerNorm + PReLU ----------------
__global__ void ln_prelu_k(const float* __restrict__ T, const float* __restrict__ g,
                           const float* __restrict__ b, const float* __restrict__ a_ptr,
                           float* __restrict__ out, h16* __restrict__ oh) {
    int row = blockIdx.x;
    const float* t = T + (size_t)row * HD;
    __shared__ float red[128];
    int tid = threadIdx.x;
    float v[4]; float s = 0.f;
    #pragma unroll
    for (int i = 0; i < 4; i++) { v[i] = t[tid + i * 128]; s += v[i]; }
    red[tid] = s; __syncthreads();
    for (int st = 64; st > 0; st >>= 1) {
        if (tid < st) red[tid] += red[tid + st];
        __syncthreads();
    }
    float mu = red[0] / HD; __syncthreads();
    float s2 = 0.f;
    #pragma unroll
    for (int i = 0; i < 4; i++) { float d = v[i] - mu; s2 += d * d; }
    red[tid] = s2; __syncthreads();
    for (int st = 64; st > 0; st >>= 1) {
        if (tid < st) red[tid] += red[tid + st];
        __syncthreads();
    }
    float inv = rsqrtf(red[0] / HD + LNEPS);
    float a = *a_ptr;
    #pragma unroll
    for (int i = 0; i < 4; i++) {
        int c = tid + i * 128;
        float o = (v[i] - mu) * inv * g[c] + b[c];
        o = (o >= 0.f) ? o : a * o;
        size_t idx = (size_t)row * HD + c;
        out[idx] = o;
        oh[idx] = toh(o);
    }
}

// ---------------- classifier + log-softmax ----------------
__global__ void cls_k(const float* __restrict__ X, const float* __restrict__ W,
                      const float* __restrict__ b, float* __restrict__ out) {
    int t = threadIdx.x;
    int r = blockIdx.x * 8 + (t >> 4);
    int c = t & 15;
    const float* x = X + (size_t)r * HD;
    float acc = 0.f;
    for (int k = 0; k < HD; k++) acc += x[k] * W[k * NC + c];
    out[(size_t)r * NC + c] = acc + b[c];
}
__global__ void logsoftmax_k(const float* __restrict__ L, float* __restrict__ out) {
    int row = blockIdx.x * 256 + threadIdx.x;
    if (row >= NN) return;
    const float* l = L + (size_t)row * NC;
    float mx = -1e30f;
    #pragma unroll
    for (int i = 0; i < NC; i++) mx = fmaxf(mx, l[i]);
    float s = 0.f;
    #pragma unroll
    for (int i = 0; i < NC; i++) s += __expf(l[i] - mx);
    float lse = mx + logf(s);
    #pragma unroll
    for (int i = 0; i < NC; i++) out[(size_t)row * NC + i] = l[i] - lse;
}

// ---------------- host ----------------
static void tg(const h16* Ah, int lda, long long sA,
               const h16* Bh, int ldb, long long sB,
               float* C, h16* Ch, int ldc, long long sC,
               const float* bias, const float* resid, int ldr, long long sR,
               float alpha, float rscale, int M, int N, int K) {
    TG p;
    p.Ah = Ah; p.Bh = Bh;
    p.C = C; p.Ch = Ch;
    p.bias = bias; p.resid = resid;
    p.sA = sA; p.sB = sB; p.sC = sC; p.sR = sR;
    p.lda = lda; p.ldb = ldb; p.ldc = ldc; p.ldr = ldr;
    p.alpha = alpha; p.rscale = rscale;
    p.K = K;
    dim3 grid(N / 128, M / 128, 1);
    const int smem = 2 * (128 * 40 + 128 * 40) * 2;   // 40960 B
    cudaFuncSetAttribute(hgemm_k, cudaFuncAttributeMaxDynamicSharedMemorySize, smem);
    hgemm_k<<<grid, 256, smem>>>(p);
}

extern "C" void kernel_launch(void* const* d_in, const int* in_sizes, int n_in,
                              void* d_out, int out_size) {
    const float* X0      = (const float*)d_in[0];
    const float* H       = (const float*)d_in[1];
    const float* w_feat  = (const float*)d_in[2];
    const float* b_feat  = (const float*)d_in[3];
    const float* Wq      = (const float*)d_in[4];
    const float* bq      = (const float*)d_in[5];
    const float* Wk      = (const float*)d_in[6];
    const float* bk      = (const float*)d_in[7];
    const float* Wv      = (const float*)d_in[8];
    const float* bv      = (const float*)d_in[9];
    const float* Wo      = (const float*)d_in[10];
    const float* bo      = (const float*)d_in[11];
    const float* ln_g    = (const float*)d_in[12];
    const float* ln_b    = (const float*)d_in[13];
    const float* prelu_a = (const float*)d_in[14];
    const float* w_cls   = (const float*)d_in[15];
    const float* b_cls   = (const float*)d_in[16];
    float* out = (float*)d_out;

    float *Y, *Xa, *Xb, *Vf, *GV, *T, *dv2, *invDE;
    int *elist, *ecnt, *nlist, *ncnt;
    h16 *Xah, *Xbh, *X0h, *Qh, *Kh, *VTh, *CTXh, *WTh;
    cudaGetSymbolAddress((void**)&Y, g_Y);
    cudaGetSymbolAddress((void**)&elist, g_elist);
    cudaGetSymbolAddress((void**)&ecnt, g_ecnt);
    cudaGetSymbolAddress((void**)&nlist, g_nlist);
    cudaGetSymbolAddress((void**)&ncnt, g_ncnt);
    cudaGetSymbolAddress((void**)&Xa, g_Xa);
    cudaGetSymbolAddress((void**)&Xah, g_Xah);
    cudaGetSymbolAddress((void**)&Xb, g_Xb);
    cudaGetSymbolAddress((void**)&Xbh, g_Xbh);
    cudaGetSymbolAddress((void**)&X0h, g_X0h);
    cudaGetSymbolAddress((void**)&Qh, g_Qh);
    cudaGetSymbolAddress((void**)&Kh, g_Kh);
    cudaGetSymbolAddress((void**)&Vf, g_Vf);
    cudaGetSymbolAddress((void**)&VTh, g_VTh);
    cudaGetSymbolAddress((void**)&GV, g_GV);
    cudaGetSymbolAddress((void**)&CTXh, g_CTXh);
    cudaGetSymbolAddress((void**)&T, g_T);
    cudaGetSymbolAddress((void**)&dv2, g_dv2);
    cudaGetSymbolAddress((void**)&invDE, g_invDE);
    cudaGetSymbolAddress((void**)&WTh, g_WTh);

    cudaFuncSetAttribute(flash_k, cudaFuncAttributeMaxDynamicSharedMemorySize, FSMEM);

    // adjacency + degrees
    zero_i_k<<<(EE + 255) / 256, 256>>>(ecnt, EE);
    zero_i_k<<<(NN + 255) / 256, 256>>>(ncnt, NN);
    build_k<<<NN, 256>>>(H, elist, ecnt, nlist, ncnt);
    deg_k<<<(NN + 255) / 256, 256>>>(ecnt, ncnt, invDE, dv2);

    // operand prep
    split_k<<<(NN * FF + 255) / 256, 256>>>(X0, X0h, (long long)NN * FF);
    dim3 tb(32, 8);
    tsplit_k<<<dim3(HD / 32, FF / 32), tb>>>(w_feat, WTh, FF, HD);
    for (int l = 0; l < NL; l++) {
        size_t w0 = (size_t)l * HD * HD;
        const float* ws[4] = {Wq + w0, Wk + w0, Wv + w0, Wo + w0};
        for (int j = 0; j < 4; j++) {
            size_t o = (1 + 4 * (size_t)l + j) * HD * HD;
            tsplit_k<<<dim3(HD / 32, HD / 32), tb>>>(ws[j], WTh + o, HD, HD);
        }
    }

    // input projection
    tg(X0h, FF, 0, WTh, FF, 0,
       Xa, Xah, HD, 0, b_feat, 0, 0, 0, 1.f, 0.f, NN, HD, FF);

    float* xf = Xa; h16* xh = Xah;
    float* yf = Xb; h16* yh = Xbh;
    for (int l = 0; l < NL; l++) {
        size_t wq_ = (1 + 4 * (size_t)l + 0) * HD * HD;
        size_t wk_ = (1 + 4 * (size_t)l + 1) * HD * HD;
        size_t wv_ = (1 + 4 * (size_t)l + 2) * HD * HD;
        size_t wo_ = (1 + 4 * (size_t)l + 3) * HD * HD;

        tg(xh, HD, 0, WTh + wq_, HD, 0,
           0, Qh, HD, 0, bq + (size_t)l * HD, 0, 0, 0, 1.f, 0.f, NN, HD, HD);
        tg(xh, HD, 0, WTh + wk_, HD, 0,
           0, Kh, HD, 0, bk + (size_t)l * HD, 0, 0, 0, 1.f, 0.f, NN, HD, HD);
        tg(xh, HD, 0, WTh + wv_, HD, 0,
           Vf, 0, HD, 0, bv + (size_t)l * HD, 0, 0, 0, 1.f, 0.f, NN, HD, HD);

        tsplit_k<<<dim3(HD / 32, NN / 32), tb>>>(Vf, VTh, NN, HD);

        // sparse GV
        spmm_edge_k<<<EE, 128>>>(elist, ecnt, dv2, invDE, Vf, Y);
        spmm_node_k<<<NN, 128>>>(nlist, ncnt, dv2, Y, GV);

        // fused attention: CTX = 0.5*softmax(QK^T/8)V + GV
        flash_k<<<dim3(NN / 128, NH), 256, FSMEM>>>(Qh, Kh, VTh, GV, CTXh);

        // T = CTX @ Wo + bo + x
        tg(CTXh, HD, 0, WTh + wo_, HD, 0,
           T, 0, HD, 0, bo + (size_t)l * HD, xf, HD, 0, 1.f, 1.f, NN, HD, HD);

        ln_prelu_k<<<NN, 128>>>(T, ln_g + (size_t)l * HD, ln_b + (size_t)l * HD,
                                prelu_a + l, yf, yh);

        float* tf = xf; xf = yf; yf = tf;
        h16* th = xh; xh = yh; yh = th;
    }

    cls_k<<<NN / 8, 128>>>(xf, w_cls, b_cls, T);
    logsoftmax_k<<<NN / 256, 256>>>(T, out);
}